// round 10
// baseline (speedup 1.0000x reference)
#include <cuda_runtime.h>
#include <cuda_fp16.h>
#include <cuda_bf16.h>
#include <mma.h>
#include <stdint.h>
#include <math.h>

using namespace nvcuda;

#define N_NODES 100000
#define E_EDGES 1600000
#define DD 128
#define SCAN_BS 512
#define NB ((N_NODES + SCAN_BS - 1) / SCAN_BS)   // 196

// ---------------- scratch (device globals; no allocations) ----------------
__device__ float  g_q [N_NODES * DD];      // [N][128] fp32, rel_pri/sqrt_dk folded in
__device__ __half g_kv[N_NODES * 2 * DD];  // [N][256]: k' (128) then v' (128)
__device__ float  g_t [N_NODES * DD];      // aggregated messages
__device__ float  g_Wb[3 * 128 * 128];     // composed projection weights fp32, [j][k]
__device__ float  g_Wa[128 * 128];         // output weights fp32, [j][k]
__device__ float  g_beff[384];
__device__ int    g_cnt     [N_NODES];
__device__ int    g_rowstart[N_NODES];
__device__ int    g_cursor  [N_NODES];
__device__ int    g_csr_src [E_EDGES];
__device__ int    g_bsums   [256];

// ---------------- zero the histogram ----------------
__global__ void zero_cnt_kernel() {
    int i = blockIdx.x * blockDim.x + threadIdx.x;
    if (i < N_NODES) g_cnt[i] = 0;
}

// ---------------- compose weights -> plain [j][k] fp32 ----------------
__global__ void build_weights(const float* __restrict__ Wk, const float* __restrict__ Wq,
                              const float* __restrict__ Wv, const float* __restrict__ Wa,
                              const float* __restrict__ rel_att, const float* __restrict__ rel_msg,
                              const float* __restrict__ rel_pri) {
    int idx = blockIdx.x * blockDim.x + threadIdx.x;   // 65536 threads
    int j = idx >> 7;        // 0..511
    int k = idx & 127;
    float val;
    if (j < 128) {
        val = Wq[j * DD + k] * rel_pri[j >> 4] * 0.25f;    // rel_pri[h]/sqrt(DK)
    } else if (j < 384) {
        int jj = (j - 128) & 127;
        const float* W = (j < 256) ? Wk : Wv;
        const float* R = (j < 256) ? rel_att : rel_msg;
        int hh = jj >> 4, e = jj & 15;
        float s = 0.f;
#pragma unroll
        for (int d2 = 0; d2 < 16; d2++)
            s += W[(hh * 16 + d2) * DD + k] * R[hh * 256 + d2 * 16 + e];
        val = s;
    } else {
        val = Wa[(j - 384) * DD + k];
    }
    if (j < 384) g_Wb[j * 128 + k] = val;
    else         g_Wa[(j - 384) * 128 + k] = val;
}

__global__ void build_bias(const float* __restrict__ bk, const float* __restrict__ bq,
                           const float* __restrict__ bv,
                           const float* __restrict__ rel_att, const float* __restrict__ rel_msg,
                           const float* __restrict__ rel_pri) {
    int j = threadIdx.x;   // 384 threads
    if (j >= 384) return;
    float val;
    if (j < 128) {
        val = bq[j] * rel_pri[j >> 4] * 0.25f;
    } else {
        int jj = (j - 128) & 127;
        const float* b = (j < 256) ? bk : bv;
        const float* R = (j < 256) ? rel_att : rel_msg;
        int hh = jj >> 4, e = jj & 15;
        float s = 0.f;
#pragma unroll
        for (int d2 = 0; d2 < 16; d2++)
            s += b[hh * 16 + d2] * R[hh * 256 + d2 * 16 + e];
        val = s;
    }
    g_beff[j] = val;
}

// ---------------- CSR build ----------------
__global__ void hist_kernel(const int* __restrict__ dst, int E) {
    int e = blockIdx.x * blockDim.x + threadIdx.x;
    if (e < E) atomicAdd(&g_cnt[dst[e]], 1);
}

__global__ void scan1_kernel() {
    __shared__ int sdata[SCAN_BS];
    int tid = threadIdx.x;
    int i = blockIdx.x * SCAN_BS + tid;
    int v = (i < N_NODES) ? g_cnt[i] : 0;
    sdata[tid] = v;
    __syncthreads();
#pragma unroll
    for (int off = 1; off < SCAN_BS; off <<= 1) {
        int x = (tid >= off) ? sdata[tid - off] : 0;
        __syncthreads();
        sdata[tid] += x;
        __syncthreads();
    }
    if (i < N_NODES) g_rowstart[i] = sdata[tid] - v;
    if (tid == SCAN_BS - 1) g_bsums[blockIdx.x] = sdata[tid];
}

__global__ void scan2_kernel() {
    __shared__ int sdata[256];
    int tid = threadIdx.x;
    int v = (tid < NB) ? g_bsums[tid] : 0;
    sdata[tid] = v;
    __syncthreads();
#pragma unroll
    for (int off = 1; off < 256; off <<= 1) {
        int x = (tid >= off) ? sdata[tid - off] : 0;
        __syncthreads();
        sdata[tid] += x;
        __syncthreads();
    }
    g_bsums[tid] = sdata[tid] - v;
}

__global__ void scan3_kernel() {
    int i = blockIdx.x * SCAN_BS + threadIdx.x;
    if (i < N_NODES) {
        int r = g_rowstart[i] + g_bsums[i >> 9];
        g_rowstart[i] = r;
        g_cursor[i] = r;
    }
}

__global__ void scatter_kernel(const int* __restrict__ src, const int* __restrict__ dst, int E) {
    int e = blockIdx.x * blockDim.x + threadIdx.x;
    if (e < E) {
        int p = atomicAdd(&g_cursor[dst[e]], 1);
        g_csr_src[p] = src[e];
    }
}

// ---------------- TF32 wmma GEMM: C[128, NT*128] = A[128,128] @ W^T ----------------
// MODE 0: A = h, W = g_Wb (3 n-tiles), +bias -> g_q fp32 / g_kv fp16
// MODE 1: A = g_t, W = g_Wa, out = alpha*(acc+ba) + (1-alpha)*h
#define ALD 132                               // fp32 leading dim (smem)
#define MT  128
#define SM_A 0
#define SM_B (MT * ALD * 4)                   // 67584
#define SM_C SM_B                             // C (128*132*4) aliases B
#define TC_SMEM (2 * MT * ALD * 4)            // 135168

template <int MODE>
__global__ void __launch_bounds__(256, 1)
tc_gemm(const float* __restrict__ Ain, int nrows,
        const float* __restrict__ ba, const float* __restrict__ haux,
        const float* __restrict__ skip, float* __restrict__ outp) {
    constexpr int NT = (MODE == 0) ? 3 : 1;
    extern __shared__ char smem[];
    float* As = (float*)(smem + SM_A);
    float* Bs = (float*)(smem + SM_B);
    float* Cs = (float*)(smem + SM_C);

    const int tid = threadIdx.x;
    const int wid = tid >> 5;
    const int m0 = blockIdx.x * MT;
    const int warp_m = wid >> 2;       // 2 warps over M, 64 rows each
    const int warp_n = wid & 3;        // 4 warps over N, 32 cols each

    // ---- load A tile (fp32, 128x128) ----
    {
        const float* Ap = (MODE == 0) ? Ain : g_t;
        int row = tid >> 1;
        int c0 = (tid & 1) << 6;
        bool vrow = (m0 + row) < nrows;
        const float* arow = Ap + (size_t)(m0 + row) * DD + c0;
        float* as = As + row * ALD + c0;
#pragma unroll
        for (int cc = 0; cc < 16; cc++) {
            float4 v = vrow ? *(const float4*)(arow + cc * 4) : make_float4(0.f, 0.f, 0.f, 0.f);
            *(float4*)(as + cc * 4) = v;
        }
    }

    float alpha = 0.f, beta = 0.f;
    if (MODE == 1) {
        float s = __ldg(skip);
        alpha = 1.f / (1.f + __expf(-s));
        beta = 1.f - alpha;
    }

    for (int nt = 0; nt < NT; nt++) {
        __syncthreads();
        // ---- load B n-tile (128x128 fp32, [j][k]) ----
        {
            const float4* sw = (const float4*)((MODE == 0) ? (g_Wb + nt * 16384) : g_Wa);
#pragma unroll
            for (int i = 0; i < 16; i++) {
                int u = tid + i * 256;          // 0..4095
                int j = u >> 5, q = u & 31;     // row j (128 floats = 32 float4)
                *(float4*)(Bs + j * ALD + q * 4) = sw[u];
            }
        }
        __syncthreads();

        // ---- tf32 mainloop: warp tile 64x32, acc[4][2] ----
        wmma::fragment<wmma::accumulator, 16, 16, 8, float> acc[4][2];
#pragma unroll
        for (int i = 0; i < 4; i++)
#pragma unroll
            for (int j = 0; j < 2; j++) wmma::fill_fragment(acc[i][j], 0.f);

#pragma unroll
        for (int ks = 0; ks < 16; ks++) {
            const int kk = ks * 8;
            wmma::fragment<wmma::matrix_a, 16, 16, 8, wmma::precision::tf32, wmma::row_major> af[4];
#pragma unroll
            for (int i = 0; i < 4; i++) {
                wmma::load_matrix_sync(af[i], As + (warp_m * 64 + i * 16) * ALD + kk, ALD);
#pragma unroll
                for (int t = 0; t < af[i].num_elements; t++)
                    af[i].x[t] = wmma::__float_to_tf32(af[i].x[t]);
            }
            wmma::fragment<wmma::matrix_b, 16, 16, 8, wmma::precision::tf32, wmma::col_major> bf[2];
#pragma unroll
            for (int j = 0; j < 2; j++) {
                wmma::load_matrix_sync(bf[j], Bs + (warp_n * 32 + j * 16) * ALD + kk, ALD);
#pragma unroll
                for (int t = 0; t < bf[j].num_elements; t++)
                    bf[j].x[t] = wmma::__float_to_tf32(bf[j].x[t]);
            }
#pragma unroll
            for (int i = 0; i < 4; i++)
#pragma unroll
                for (int j = 0; j < 2; j++)
                    wmma::mma_sync(acc[i][j], af[i], bf[j], acc[i][j]);
        }

        // ---- stage accumulators to C smem (aliases B; mma reads done) ----
        __syncthreads();
#pragma unroll
        for (int i = 0; i < 4; i++)
#pragma unroll
            for (int j = 0; j < 2; j++)
                wmma::store_matrix_sync(Cs + (warp_m * 64 + i * 16) * ALD + warp_n * 32 + j * 16,
                                        acc[i][j], ALD, wmma::mem_row_major);
        __syncthreads();

        // ---- epilogue: coalesced writes from C smem ----
        {
            int row = tid >> 1;
            int c0 = (tid & 1) << 6;
            int grow = m0 + row;
            if (grow < nrows) {
                const float* crow = Cs + row * ALD + c0;
                const int jb = nt * 128 + c0;
                if (MODE == 0) {
                    if (nt == 0) {
                        float* dst = g_q + (size_t)grow * DD + c0;
#pragma unroll
                        for (int cc = 0; cc < 16; cc++) {
                            float4 o = *(const float4*)(crow + cc * 4);
                            o.x += g_beff[jb + cc * 4];
                            o.y += g_beff[jb + cc * 4 + 1];
                            o.z += g_beff[jb + cc * 4 + 2];
                            o.w += g_beff[jb + cc * 4 + 3];
                            *(float4*)(dst + cc * 4) = o;
                        }
                    } else {
                        __half* dst = g_kv + (size_t)grow * 256 + (nt - 1) * 128 + c0;
#pragma unroll
                        for (int cc = 0; cc < 8; cc++) {
                            uint4 u;
                            unsigned* up = &u.x;
#pragma unroll
                            for (int p = 0; p < 4; p++) {
                                int c = cc * 8 + p * 2;
                                float f0 = crow[c]     + g_beff[jb + c];
                                float f1 = crow[c + 1] + g_beff[jb + c + 1];
                                __half2 hh = __floats2half2_rn(f0, f1);
                                up[p] = *(unsigned*)&hh;
                            }
                            *(uint4*)(dst + cc * 8) = u;
                        }
                    }
                } else {
                    float* dst = outp + (size_t)grow * DD + c0;
                    const float* hrow = haux + (size_t)grow * DD + c0;
#pragma unroll
                    for (int cc = 0; cc < 16; cc++) {
                        float4 hv = *(const float4*)(hrow + cc * 4);
                        float4 o;
                        o.x = alpha * (crow[cc * 4]     + ba[c0 + cc * 4])     + beta * hv.x;
                        o.y = alpha * (crow[cc * 4 + 1] + ba[c0 + cc * 4 + 1]) + beta * hv.y;
                        o.z = alpha * (crow[cc * 4 + 2] + ba[c0 + cc * 4 + 2]) + beta * hv.z;
                        o.w = alpha * (crow[cc * 4 + 3] + ba[c0 + cc * 4 + 3]) + beta * hv.w;
                        *(float4*)(dst + cc * 4) = o;
                    }
                }
            }
        }
    }
}

// ---------------- fused edge softmax + aggregation: one warp per dst node ----------------
__global__ void attn_kernel() {
    int w = (blockIdx.x * blockDim.x + threadIdx.x) >> 5;
    int t = threadIdx.x & 31;
    if (w >= N_NODES) return;
    const int d = w;

    float4 q4 = *(const float4*)(g_q + (size_t)d * DD + t * 4);
    int start = g_rowstart[d];
    int cnt = g_cnt[d];

    float4 acc = make_float4(0.f, 0.f, 0.f, 0.f);
    float den = 0.f;
    const int* __restrict__ cs = g_csr_src + start;

    int i = 0;
    for (; i + 2 <= cnt; i += 2) {
        int s0 = cs[i];
        int s1 = cs[i + 1];
        const uint2* __restrict__ r0 = reinterpret_cast<const uint2*>(g_kv + (size_t)s0 * 256);
        const uint2* __restrict__ r1 = reinterpret_cast<const uint2*>(g_kv + (size_t)s1 * 256);
        uint2 ku0 = r0[t];
        uint2 vu0 = r0[32 + t];
        uint2 ku1 = r1[t];
        uint2 vu1 = r1[32 + t];

        float2 k01 = __half22float2(*reinterpret_cast<__half2*>(&ku0.x));
        float2 k23 = __half22float2(*reinterpret_cast<__half2*>(&ku0.y));
        float p0 = q4.x * k01.x + q4.y * k01.y + q4.z * k23.x + q4.w * k23.y;
        float2 m01 = __half22float2(*reinterpret_cast<__half2*>(&ku1.x));
        float2 m23 = __half22float2(*reinterpret_cast<__half2*>(&ku1.y));
        float p1 = q4.x * m01.x + q4.y * m01.y + q4.z * m23.x + q4.w * m23.y;

        p0 += __shfl_xor_sync(0xffffffffu, p0, 1);
        p1 += __shfl_xor_sync(0xffffffffu, p1, 1);
        p0 += __shfl_xor_sync(0xffffffffu, p0, 2);
        p1 += __shfl_xor_sync(0xffffffffu, p1, 2);
        float ex0 = __expf(p0);
        float ex1 = __expf(p1);

        float2 v01 = __half22float2(*reinterpret_cast<__half2*>(&vu0.x));
        float2 v23 = __half22float2(*reinterpret_cast<__half2*>(&vu0.y));
        float2 w01 = __half22float2(*reinterpret_cast<__half2*>(&vu1.x));
        float2 w23 = __half22float2(*reinterpret_cast<__half2*>(&vu1.y));
        den += ex0 + ex1;
        acc.x += ex0 * v01.x + ex1 * w01.x;
        acc.y += ex0 * v01.y + ex1 * w01.y;
        acc.z += ex0 * v23.x + ex1 * w23.x;
        acc.w += ex0 * v23.y + ex1 * w23.y;
    }
    if (i < cnt) {
        int s0 = cs[i];
        const uint2* __restrict__ r0 = reinterpret_cast<const uint2*>(g_kv + (size_t)s0 * 256);
        uint2 ku0 = r0[t];
        uint2 vu0 = r0[32 + t];
        float2 k01 = __half22float2(*reinterpret_cast<__half2*>(&ku0.x));
        float2 k23 = __half22float2(*reinterpret_cast<__half2*>(&ku0.y));
        float p0 = q4.x * k01.x + q4.y * k01.y + q4.z * k23.x + q4.w * k23.y;
        p0 += __shfl_xor_sync(0xffffffffu, p0, 1);
        p0 += __shfl_xor_sync(0xffffffffu, p0, 2);
        float ex0 = __expf(p0);
        float2 v01 = __half22float2(*reinterpret_cast<__half2*>(&vu0.x));
        float2 v23 = __half22float2(*reinterpret_cast<__half2*>(&vu0.y));
        den += ex0;
        acc.x += ex0 * v01.x;
        acc.y += ex0 * v01.y;
        acc.z += ex0 * v23.x;
        acc.w += ex0 * v23.y;
    }
    float inv = (cnt > 0) ? (1.f / den) : 0.f;
    float4 o = make_float4(acc.x * inv, acc.y * inv, acc.z * inv, acc.w * inv);
    *(float4*)(g_t + (size_t)d * DD + t * 4) = o;
}

// ---------------- launch ----------------
extern "C" void kernel_launch(void* const* d_in, const int* in_sizes, int n_in,
                              void* d_out, int out_size) {
    const float* h       = (const float*)d_in[0];
    const int*   src     = (const int*)d_in[1];
    const int*   dst     = (const int*)d_in[2];
    const float* Wk      = (const float*)d_in[3];
    const float* bk      = (const float*)d_in[4];
    const float* Wq      = (const float*)d_in[5];
    const float* bq      = (const float*)d_in[6];
    const float* Wv      = (const float*)d_in[7];
    const float* bv      = (const float*)d_in[8];
    const float* Wa      = (const float*)d_in[9];
    const float* ba      = (const float*)d_in[10];
    const float* rel_att = (const float*)d_in[11];
    const float* rel_msg = (const float*)d_in[12];
    const float* rel_pri = (const float*)d_in[13];
    const float* skip    = (const float*)d_in[14];

    const int n = in_sizes[0] / DD;   // 100000
    const int E = in_sizes[1];        // 1600000
    const int mtiles = (n + MT - 1) / MT;   // 782

    static cudaStream_t s2 = nullptr;
    static cudaEvent_t ev_fork = nullptr, ev_join = nullptr;
    static bool attr_done = false;
    if (!s2) {
        cudaStreamCreateWithFlags(&s2, cudaStreamNonBlocking);
        cudaEventCreateWithFlags(&ev_fork, cudaEventDisableTiming);
        cudaEventCreateWithFlags(&ev_join, cudaEventDisableTiming);
    }
    if (!attr_done) {
        cudaFuncSetAttribute(tc_gemm<0>, cudaFuncAttributeMaxDynamicSharedMemorySize, TC_SMEM);
        cudaFuncSetAttribute(tc_gemm<1>, cudaFuncAttributeMaxDynamicSharedMemorySize, TC_SMEM);
        attr_done = true;
    }

    // fork: CSR chain on s2
    cudaEventRecord(ev_fork, 0);
    cudaStreamWaitEvent(s2, ev_fork, 0);

    // launch order keeps tc_gemm<0> in ncu's profiled slot (4th launch)
    build_weights<<<256, 256>>>(Wk, Wq, Wv, Wa, rel_att, rel_msg, rel_pri);      // 1
    build_bias<<<1, 384>>>(bk, bq, bv, rel_att, rel_msg, rel_pri);               // 2
    zero_cnt_kernel<<<(N_NODES + 255) / 256, 256, 0, s2>>>();                    // 3
    tc_gemm<0><<<mtiles, 256, TC_SMEM>>>(h, n, nullptr, nullptr, nullptr, nullptr); // 4 <- profiled

    hist_kernel<<<(E + 255) / 256, 256, 0, s2>>>(dst, E);
    scan1_kernel<<<NB, SCAN_BS, 0, s2>>>();
    scan2_kernel<<<1, 256, 0, s2>>>();
    scan3_kernel<<<NB, SCAN_BS, 0, s2>>>();
    scatter_kernel<<<(E + 255) / 256, 256, 0, s2>>>(src, dst, E);
    cudaEventRecord(ev_join, s2);

    // join: attn needs both CSR and projections
    cudaStreamWaitEvent(0, ev_join, 0);
    attn_kernel<<<(n * 32 + 255) / 256, 256>>>();
    tc_gemm<1><<<mtiles, 256, TC_SMEM>>>(nullptr, n, ba, h, skip, (float*)d_out);
}

// round 11
// speedup vs baseline: 1.2168x; 1.2168x over previous
#include <cuda_runtime.h>
#include <cuda_fp16.h>
#include <cuda_bf16.h>
#include <mma.h>
#include <stdint.h>
#include <math.h>

using namespace nvcuda;

#define N_NODES 100000
#define E_EDGES 1600000
#define DD 128
#define SCAN_BS 512
#define NB ((N_NODES + SCAN_BS - 1) / SCAN_BS)   // 196

// ---------------- scratch (device globals; no allocations) ----------------
__device__ float          g_q [N_NODES * DD];      // [N][128] fp32, rel_pri/sqrt_dk folded in
__device__ __half         g_kv[N_NODES * 2 * DD];  // [N][256]: k' (128) then v' (128)
__device__ float          g_t [N_NODES * DD];      // aggregated messages
__device__ __nv_bfloat16  g_Wbhi[3 * 128 * 128];   // composed projection weights bf16 hi, [j][k]
__device__ __nv_bfloat16  g_Wblo[3 * 128 * 128];
__device__ __nv_bfloat16  g_Wahi[128 * 128];       // output weights bf16 hi, [j][k]
__device__ __nv_bfloat16  g_Walo[128 * 128];
__device__ float          g_beff[384];
__device__ int            g_cnt     [N_NODES];
__device__ int            g_rowstart[N_NODES];
__device__ int            g_cursor  [N_NODES];
__device__ int            g_csr_src [E_EDGES];
__device__ int            g_bsums   [256];

// ---------------- zero the histogram ----------------
__global__ void zero_cnt_kernel() {
    int i = blockIdx.x * blockDim.x + threadIdx.x;
    if (i < N_NODES) g_cnt[i] = 0;
}

// ---------------- compose weights -> plain [j][k] bf16 hi/lo ----------------
__global__ void build_weights(const float* __restrict__ Wk, const float* __restrict__ Wq,
                              const float* __restrict__ Wv, const float* __restrict__ Wa,
                              const float* __restrict__ rel_att, const float* __restrict__ rel_msg,
                              const float* __restrict__ rel_pri) {
    int idx = blockIdx.x * blockDim.x + threadIdx.x;   // 65536 threads
    int j = idx >> 7;        // 0..511
    int k = idx & 127;
    float val;
    if (j < 128) {
        val = Wq[j * DD + k] * rel_pri[j >> 4] * 0.25f;    // rel_pri[h]/sqrt(DK)
    } else if (j < 384) {
        int jj = (j - 128) & 127;
        const float* W = (j < 256) ? Wk : Wv;
        const float* R = (j < 256) ? rel_att : rel_msg;
        int hh = jj >> 4, e = jj & 15;
        float s = 0.f;
#pragma unroll
        for (int d2 = 0; d2 < 16; d2++)
            s += W[(hh * 16 + d2) * DD + k] * R[hh * 256 + d2 * 16 + e];
        val = s;
    } else {
        val = Wa[(j - 384) * DD + k];
    }
    __nv_bfloat16 hi = __float2bfloat16(val);
    __nv_bfloat16 lo = __float2bfloat16(val - __bfloat162float(hi));
    if (j < 384) {
        g_Wbhi[j * 128 + k] = hi;
        g_Wblo[j * 128 + k] = lo;
    } else {
        g_Wahi[(j - 384) * 128 + k] = hi;
        g_Walo[(j - 384) * 128 + k] = lo;
    }
}

__global__ void build_bias(const float* __restrict__ bk, const float* __restrict__ bq,
                           const float* __restrict__ bv,
                           const float* __restrict__ rel_att, const float* __restrict__ rel_msg,
                           const float* __restrict__ rel_pri) {
    int j = threadIdx.x;   // 384 threads
    if (j >= 384) return;
    float val;
    if (j < 128) {
        val = bq[j] * rel_pri[j >> 4] * 0.25f;
    } else {
        int jj = (j - 128) & 127;
        const float* b = (j < 256) ? bk : bv;
        const float* R = (j < 256) ? rel_att : rel_msg;
        int hh = jj >> 4, e = jj & 15;
        float s = 0.f;
#pragma unroll
        for (int d2 = 0; d2 < 16; d2++)
            s += b[hh * 16 + d2] * R[hh * 256 + d2 * 16 + e];
        val = s;
    }
    g_beff[j] = val;
}

// ---------------- CSR build ----------------
__global__ void hist_kernel(const int* __restrict__ dst, int E) {
    int e = blockIdx.x * blockDim.x + threadIdx.x;
    if (e < E) atomicAdd(&g_cnt[dst[e]], 1);
}

__global__ void scan1_kernel() {
    __shared__ int sdata[SCAN_BS];
    int tid = threadIdx.x;
    int i = blockIdx.x * SCAN_BS + tid;
    int v = (i < N_NODES) ? g_cnt[i] : 0;
    sdata[tid] = v;
    __syncthreads();
#pragma unroll
    for (int off = 1; off < SCAN_BS; off <<= 1) {
        int x = (tid >= off) ? sdata[tid - off] : 0;
        __syncthreads();
        sdata[tid] += x;
        __syncthreads();
    }
    if (i < N_NODES) g_rowstart[i] = sdata[tid] - v;
    if (tid == SCAN_BS - 1) g_bsums[blockIdx.x] = sdata[tid];
}

__global__ void scan2_kernel() {
    __shared__ int sdata[256];
    int tid = threadIdx.x;
    int v = (tid < NB) ? g_bsums[tid] : 0;
    sdata[tid] = v;
    __syncthreads();
#pragma unroll
    for (int off = 1; off < 256; off <<= 1) {
        int x = (tid >= off) ? sdata[tid - off] : 0;
        __syncthreads();
        sdata[tid] += x;
        __syncthreads();
    }
    g_bsums[tid] = sdata[tid] - v;
}

__global__ void scan3_kernel() {
    int i = blockIdx.x * SCAN_BS + threadIdx.x;
    if (i < N_NODES) {
        int r = g_rowstart[i] + g_bsums[i >> 9];
        g_rowstart[i] = r;
        g_cursor[i] = r;
    }
}

__global__ void scatter_kernel(const int* __restrict__ src, const int* __restrict__ dst, int E) {
    int e = blockIdx.x * blockDim.x + threadIdx.x;
    if (e < E) {
        int p = atomicAdd(&g_cursor[dst[e]], 1);
        g_csr_src[p] = src[e];
    }
}

// ---------------- wmma GEMM: C[128, NT*128] = A[128,128] @ W^T, bf16x3 split ----------------
// MODE 0: A = h, W = g_Wbhi/lo (3 n-tiles in-block loop), +bias -> g_q fp32 / g_kv fp16
// MODE 1: A = g_t, W = g_Wahi/lo, out = alpha*(acc+ba) + (1-alpha)*h
#define ALD 136                               // bf16 leading dim (272B rows: conflict-free, 16B aligned)
#define CLD 132                               // f32 C leading dim
#define SM_AHI 0
#define SM_ALO (128 * ALD * 2)                // 34816
#define SM_BHI (2 * 128 * ALD * 2)            // 69632
#define SM_BLO (SM_BHI + 128 * ALD * 2)
#define SM_C   SM_BHI                         // C tile aliases B (B reloaded per nt)
#define TC_SMEM (4 * 128 * ALD * 2)           // 139264

template <int MODE>
__global__ void __launch_bounds__(256, 1)
tc_gemm(const float* __restrict__ Ain, int nrows,
        const float* __restrict__ ba, const float* __restrict__ haux,
        const float* __restrict__ skip, float* __restrict__ outp) {
    constexpr int NT = (MODE == 0) ? 3 : 1;
    extern __shared__ char smem[];
    __nv_bfloat16* Ah = (__nv_bfloat16*)(smem + SM_AHI);
    __nv_bfloat16* Al = (__nv_bfloat16*)(smem + SM_ALO);
    __nv_bfloat16* Bh = (__nv_bfloat16*)(smem + SM_BHI);
    __nv_bfloat16* Bl = (__nv_bfloat16*)(smem + SM_BLO);
    float*         Cs = (float*)(smem + SM_C);

    const int tid = threadIdx.x;
    const int wid = tid >> 5;
    const int m0 = blockIdx.x * 128;
    const int warp_m = wid & 3;        // 4 warps over M (32 rows each)
    const int warp_n = wid >> 2;       // 2 warps over N (64 cols each)

    // ---- load A tile (fp32 -> bf16 hi/lo) ----
    {
        const float* Ap = (MODE == 0) ? Ain : g_t;
        int row = tid >> 1;
        int c0 = (tid & 1) << 6;
        bool vrow = (m0 + row) < nrows;
        const float* arow = Ap + (size_t)(m0 + row) * DD + c0;
        __nv_bfloat16* ah = Ah + row * ALD + c0;
        __nv_bfloat16* al = Al + row * ALD + c0;
#pragma unroll
        for (int cc = 0; cc < 16; cc++) {
            float4 v = vrow ? *(const float4*)(arow + cc * 4) : make_float4(0.f, 0.f, 0.f, 0.f);
            __nv_bfloat16 h0 = __float2bfloat16(v.x), h1 = __float2bfloat16(v.y);
            __nv_bfloat16 h2 = __float2bfloat16(v.z), h3 = __float2bfloat16(v.w);
            __nv_bfloat162 ph0; ph0.x = h0; ph0.y = h1;
            __nv_bfloat162 ph1; ph1.x = h2; ph1.y = h3;
            __nv_bfloat16 l0 = __float2bfloat16(v.x - __bfloat162float(h0));
            __nv_bfloat16 l1 = __float2bfloat16(v.y - __bfloat162float(h1));
            __nv_bfloat16 l2 = __float2bfloat16(v.z - __bfloat162float(h2));
            __nv_bfloat16 l3 = __float2bfloat16(v.w - __bfloat162float(h3));
            __nv_bfloat162 pl0; pl0.x = l0; pl0.y = l1;
            __nv_bfloat162 pl1; pl1.x = l2; pl1.y = l3;
            *(uint2*)(ah + cc * 4) = make_uint2(*(unsigned*)&ph0, *(unsigned*)&ph1);
            *(uint2*)(al + cc * 4) = make_uint2(*(unsigned*)&pl0, *(unsigned*)&pl1);
        }
    }

    float alpha = 0.f, beta = 0.f;
    if (MODE == 1) {
        float s = __ldg(skip);
        alpha = 1.f / (1.f + __expf(-s));
        beta = 1.f - alpha;
    }

    for (int nt = 0; nt < NT; nt++) {
        __syncthreads();
        {
            const uint4* sh = (const uint4*)((MODE == 0) ? (g_Wbhi + nt * 16384) : g_Wahi);
            const uint4* sl = (const uint4*)((MODE == 0) ? (g_Wblo + nt * 16384) : g_Walo);
#pragma unroll
            for (int i = 0; i < 8; i++) {
                int u = tid + i * 256;
                int j = u >> 4, q = u & 15;
                *(uint4*)((char*)Bh + j * (ALD * 2) + q * 16) = sh[u];
                *(uint4*)((char*)Bl + j * (ALD * 2) + q * 16) = sl[u];
            }
        }
        __syncthreads();

        // ---- wmma mainloop: warp tile 32x64, acc = Ah*Bh + Ah*Bl + Al*Bh ----
        // unroll 1 on kstep + tight B-fragment live ranges keep regs below the
        // spill threshold (R7 hit the 254-reg cap and spilled to local).
        wmma::fragment<wmma::accumulator, 16, 16, 16, float> acc[2][4];
#pragma unroll
        for (int i = 0; i < 2; i++)
#pragma unroll
            for (int j = 0; j < 4; j++) wmma::fill_fragment(acc[i][j], 0.f);

#pragma unroll 1
        for (int ks = 0; ks < 8; ks++) {
            const int kk = ks * 16;
            wmma::fragment<wmma::matrix_a, 16, 16, 16, __nv_bfloat16, wmma::row_major> ah[2], al[2];
#pragma unroll
            for (int i = 0; i < 2; i++) {
                wmma::load_matrix_sync(ah[i], Ah + (warp_m * 32 + i * 16) * ALD + kk, ALD);
                wmma::load_matrix_sync(al[i], Al + (warp_m * 32 + i * 16) * ALD + kk, ALD);
            }
#pragma unroll
            for (int j = 0; j < 4; j++) {
                wmma::fragment<wmma::matrix_b, 16, 16, 16, __nv_bfloat16, wmma::col_major> bh, bl;
                wmma::load_matrix_sync(bh, Bh + (warp_n * 64 + j * 16) * ALD + kk, ALD);
                wmma::load_matrix_sync(bl, Bl + (warp_n * 64 + j * 16) * ALD + kk, ALD);
#pragma unroll
                for (int i = 0; i < 2; i++) {
                    wmma::mma_sync(acc[i][j], ah[i], bh, acc[i][j]);
                    wmma::mma_sync(acc[i][j], ah[i], bl, acc[i][j]);
                    wmma::mma_sync(acc[i][j], al[i], bh, acc[i][j]);
                }
            }
        }

        // ---- stage accumulators to C smem (aliases B; mma reads done) ----
        __syncthreads();
#pragma unroll
        for (int i = 0; i < 2; i++)
#pragma unroll
            for (int j = 0; j < 4; j++)
                wmma::store_matrix_sync(Cs + (warp_m * 32 + i * 16) * CLD + warp_n * 64 + j * 16,
                                        acc[i][j], CLD, wmma::mem_row_major);
        __syncthreads();

        // ---- epilogue: coalesced writes from C smem ----
        {
            int row = tid >> 1;
            int c0 = (tid & 1) << 6;
            int grow = m0 + row;
            if (grow < nrows) {
                const float* crow = Cs + row * CLD + c0;
                const int jb = nt * 128 + c0;
                if (MODE == 0) {
                    if (nt == 0) {
                        float* dst = g_q + (size_t)grow * DD + c0;
#pragma unroll
                        for (int cc = 0; cc < 16; cc++) {
                            float4 o = *(const float4*)(crow + cc * 4);
                            o.x += g_beff[jb + cc * 4];
                            o.y += g_beff[jb + cc * 4 + 1];
                            o.z += g_beff[jb + cc * 4 + 2];
                            o.w += g_beff[jb + cc * 4 + 3];
                            *(float4*)(dst + cc * 4) = o;
                        }
                    } else {
                        __half* dst = g_kv + (size_t)grow * 256 + (nt - 1) * 128 + c0;
#pragma unroll
                        for (int cc = 0; cc < 8; cc++) {
                            uint4 u;
                            unsigned* up = &u.x;
#pragma unroll
                            for (int p = 0; p < 4; p++) {
                                int c = cc * 8 + p * 2;
                                float f0 = crow[c]     + g_beff[jb + c];
                                float f1 = crow[c + 1] + g_beff[jb + c + 1];
                                __half2 hh = __floats2half2_rn(f0, f1);
                                up[p] = *(unsigned*)&hh;
                            }
                            *(uint4*)(dst + cc * 8) = u;
                        }
                    }
                } else {
                    float* dst = outp + (size_t)grow * DD + c0;
                    const float* hrow = haux + (size_t)grow * DD + c0;
#pragma unroll
                    for (int cc = 0; cc < 16; cc++) {
                        float4 hv = *(const float4*)(hrow + cc * 4);
                        float4 o;
                        o.x = alpha * (crow[cc * 4]     + ba[c0 + cc * 4])     + beta * hv.x;
                        o.y = alpha * (crow[cc * 4 + 1] + ba[c0 + cc * 4 + 1]) + beta * hv.y;
                        o.z = alpha * (crow[cc * 4 + 2] + ba[c0 + cc * 4 + 2]) + beta * hv.z;
                        o.w = alpha * (crow[cc * 4 + 3] + ba[c0 + cc * 4 + 3]) + beta * hv.w;
                        *(float4*)(dst + cc * 4) = o;
                    }
                }
            }
        }
    }
}

// ---------------- fused edge softmax + aggregation: one warp per dst node ----------------
__global__ void attn_kernel() {
    int w = (blockIdx.x * blockDim.x + threadIdx.x) >> 5;
    int t = threadIdx.x & 31;
    if (w >= N_NODES) return;
    const int d = w;

    float4 q4 = *(const float4*)(g_q + (size_t)d * DD + t * 4);
    int start = g_rowstart[d];
    int cnt = g_cnt[d];

    float4 acc = make_float4(0.f, 0.f, 0.f, 0.f);
    float den = 0.f;
    const int* __restrict__ cs = g_csr_src + start;

    int i = 0;
    for (; i + 2 <= cnt; i += 2) {
        int s0 = cs[i];
        int s1 = cs[i + 1];
        const uint2* __restrict__ r0 = reinterpret_cast<const uint2*>(g_kv + (size_t)s0 * 256);
        const uint2* __restrict__ r1 = reinterpret_cast<const uint2*>(g_kv + (size_t)s1 * 256);
        uint2 ku0 = r0[t];
        uint2 vu0 = r0[32 + t];
        uint2 ku1 = r1[t];
        uint2 vu1 = r1[32 + t];

        float2 k01 = __half22float2(*reinterpret_cast<__half2*>(&ku0.x));
        float2 k23 = __half22float2(*reinterpret_cast<__half2*>(&ku0.y));
        float p0 = q4.x * k01.x + q4.y * k01.y + q4.z * k23.x + q4.w * k23.y;
        float2 m01 = __half22float2(*reinterpret_cast<__half2*>(&ku1.x));
        float2 m23 = __half22float2(*reinterpret_cast<__half2*>(&ku1.y));
        float p1 = q4.x * m01.x + q4.y * m01.y + q4.z * m23.x + q4.w * m23.y;

        p0 += __shfl_xor_sync(0xffffffffu, p0, 1);
        p1 += __shfl_xor_sync(0xffffffffu, p1, 1);
        p0 += __shfl_xor_sync(0xffffffffu, p0, 2);
        p1 += __shfl_xor_sync(0xffffffffu, p1, 2);
        float ex0 = __expf(p0);
        float ex1 = __expf(p1);

        float2 v01 = __half22float2(*reinterpret_cast<__half2*>(&vu0.x));
        float2 v23 = __half22float2(*reinterpret_cast<__half2*>(&vu0.y));
        float2 w01 = __half22float2(*reinterpret_cast<__half2*>(&vu1.x));
        float2 w23 = __half22float2(*reinterpret_cast<__half2*>(&vu1.y));
        den += ex0 + ex1;
        acc.x += ex0 * v01.x + ex1 * w01.x;
        acc.y += ex0 * v01.y + ex1 * w01.y;
        acc.z += ex0 * v23.x + ex1 * w23.x;
        acc.w += ex0 * v23.y + ex1 * w23.y;
    }
    if (i < cnt) {
        int s0 = cs[i];
        const uint2* __restrict__ r0 = reinterpret_cast<const uint2*>(g_kv + (size_t)s0 * 256);
        uint2 ku0 = r0[t];
        uint2 vu0 = r0[32 + t];
        float2 k01 = __half22float2(*reinterpret_cast<__half2*>(&ku0.x));
        float2 k23 = __half22float2(*reinterpret_cast<__half2*>(&ku0.y));
        float p0 = q4.x * k01.x + q4.y * k01.y + q4.z * k23.x + q4.w * k23.y;
        p0 += __shfl_xor_sync(0xffffffffu, p0, 1);
        p0 += __shfl_xor_sync(0xffffffffu, p0, 2);
        float ex0 = __expf(p0);
        float2 v01 = __half22float2(*reinterpret_cast<__half2*>(&vu0.x));
        float2 v23 = __half22float2(*reinterpret_cast<__half2*>(&vu0.y));
        den += ex0;
        acc.x += ex0 * v01.x;
        acc.y += ex0 * v01.y;
        acc.z += ex0 * v23.x;
        acc.w += ex0 * v23.y;
    }
    float inv = (cnt > 0) ? (1.f / den) : 0.f;
    float4 o = make_float4(acc.x * inv, acc.y * inv, acc.z * inv, acc.w * inv);
    *(float4*)(g_t + (size_t)d * DD + t * 4) = o;
}

// ---------------- launch ----------------
extern "C" void kernel_launch(void* const* d_in, const int* in_sizes, int n_in,
                              void* d_out, int out_size) {
    const float* h       = (const float*)d_in[0];
    const int*   src     = (const int*)d_in[1];
    const int*   dst     = (const int*)d_in[2];
    const float* Wk      = (const float*)d_in[3];
    const float* bk      = (const float*)d_in[4];
    const float* Wq      = (const float*)d_in[5];
    const float* bq      = (const float*)d_in[6];
    const float* Wv      = (const float*)d_in[7];
    const float* bv      = (const float*)d_in[8];
    const float* Wa      = (const float*)d_in[9];
    const float* ba      = (const float*)d_in[10];
    const float* rel_att = (const float*)d_in[11];
    const float* rel_msg = (const float*)d_in[12];
    const float* rel_pri = (const float*)d_in[13];
    const float* skip    = (const float*)d_in[14];

    const int n = in_sizes[0] / DD;   // 100000
    const int E = in_sizes[1];        // 1600000
    const int ntiles = (n + 127) / 128;

    static cudaStream_t s2 = nullptr;
    static cudaEvent_t ev_fork = nullptr, ev_join = nullptr;
    static bool attr_done = false;
    if (!s2) {
        cudaStreamCreateWithFlags(&s2, cudaStreamNonBlocking);
        cudaEventCreateWithFlags(&ev_fork, cudaEventDisableTiming);
        cudaEventCreateWithFlags(&ev_join, cudaEventDisableTiming);
    }
    if (!attr_done) {
        cudaFuncSetAttribute(tc_gemm<0>, cudaFuncAttributeMaxDynamicSharedMemorySize, TC_SMEM);
        cudaFuncSetAttribute(tc_gemm<1>, cudaFuncAttributeMaxDynamicSharedMemorySize, TC_SMEM);
        attr_done = true;
    }

    // fork: CSR chain on s2
    cudaEventRecord(ev_fork, 0);
    cudaStreamWaitEvent(s2, ev_fork, 0);

    // launch order keeps tc_gemm<0> in ncu's profiled slot (4th launch)
    build_weights<<<256, 256>>>(Wk, Wq, Wv, Wa, rel_att, rel_msg, rel_pri);      // 1
    build_bias<<<1, 384>>>(bk, bq, bv, rel_att, rel_msg, rel_pri);               // 2
    zero_cnt_kernel<<<(N_NODES + 255) / 256, 256, 0, s2>>>();                    // 3
    tc_gemm<0><<<ntiles, 256, TC_SMEM>>>(h, n, nullptr, nullptr, nullptr, nullptr); // 4 <- profiled

    hist_kernel<<<(E + 255) / 256, 256, 0, s2>>>(dst, E);
    scan1_kernel<<<NB, SCAN_BS, 0, s2>>>();
    scan2_kernel<<<1, 256, 0, s2>>>();
    scan3_kernel<<<NB, SCAN_BS, 0, s2>>>();
    scatter_kernel<<<(E + 255) / 256, 256, 0, s2>>>(src, dst, E);
    cudaEventRecord(ev_join, s2);

    // join: attn needs both CSR and projections
    cudaStreamWaitEvent(0, ev_join, 0);
    attn_kernel<<<(n * 32 + 255) / 256, 256>>>();
    tc_gemm<1><<<ntiles, 256, TC_SMEM>>>(nullptr, n, ba, h, skip, (float*)d_out);
}

// round 12
// speedup vs baseline: 1.3242x; 1.0883x over previous
#include <cuda_runtime.h>
#include <cuda_fp16.h>
#include <cuda_bf16.h>
#include <mma.h>
#include <stdint.h>
#include <math.h>

using namespace nvcuda;

#define N_NODES 100000
#define E_EDGES 1600000
#define DD 128
#define SCAN_BS 512
#define NB ((N_NODES + SCAN_BS - 1) / SCAN_BS)   // 196

// ---------------- scratch (device globals; no allocations) ----------------
__device__ float  g_q [N_NODES * DD];      // [N][128] fp32, rel_pri/sqrt_dk folded in
__device__ __half g_kv[N_NODES * 2 * DD];  // [N][256]: k' (128) then v' (128)
__device__ float  g_t [N_NODES * DD];      // aggregated messages
__device__ __half g_Wbhi[3 * 128 * 128];   // composed projection weights fp16 hi, [j][k]
__device__ __half g_Wblo[3 * 128 * 128];   // fp16 lo residual
__device__ __half g_Wahi[128 * 128];       // output weights fp16 hi, [j][k]
__device__ __half g_Walo[128 * 128];
__device__ float  g_beff[384];
__device__ int    g_cnt     [N_NODES];
__device__ int    g_rowstart[N_NODES];
__device__ int    g_cursor  [N_NODES];
__device__ int    g_csr_src [E_EDGES];
__device__ int    g_bsums   [256];

// ---------------- zero the histogram ----------------
__global__ void zero_cnt_kernel() {
    int i = blockIdx.x * blockDim.x + threadIdx.x;
    if (i < N_NODES) g_cnt[i] = 0;
}

// ---------------- compose weights -> plain [j][k] fp16 hi/lo ----------------
__global__ void build_weights(const float* __restrict__ Wk, const float* __restrict__ Wq,
                              const float* __restrict__ Wv, const float* __restrict__ Wa,
                              const float* __restrict__ rel_att, const float* __restrict__ rel_msg,
                              const float* __restrict__ rel_pri) {
    int idx = blockIdx.x * blockDim.x + threadIdx.x;   // 65536 threads
    int j = idx >> 7;        // 0..511
    int k = idx & 127;
    float val;
    if (j < 128) {
        val = Wq[j * DD + k] * rel_pri[j >> 4] * 0.25f;    // rel_pri[h]/sqrt(DK)
    } else if (j < 384) {
        int jj = (j - 128) & 127;
        const float* W = (j < 256) ? Wk : Wv;
        const float* R = (j < 256) ? rel_att : rel_msg;
        int hh = jj >> 4, e = jj & 15;
        float s = 0.f;
#pragma unroll
        for (int d2 = 0; d2 < 16; d2++)
            s += W[(hh * 16 + d2) * DD + k] * R[hh * 256 + d2 * 16 + e];
        val = s;
    } else {
        val = Wa[(j - 384) * DD + k];
    }
    __half hi = __float2half_rn(val);
    __half lo = __float2half_rn(val - __half2float(hi));
    if (j < 384) {
        g_Wbhi[j * 128 + k] = hi;
        g_Wblo[j * 128 + k] = lo;
    } else {
        g_Wahi[(j - 384) * 128 + k] = hi;
        g_Walo[(j - 384) * 128 + k] = lo;
    }
}

__global__ void build_bias(const float* __restrict__ bk, const float* __restrict__ bq,
                           const float* __restrict__ bv,
                           const float* __restrict__ rel_att, const float* __restrict__ rel_msg,
                           const float* __restrict__ rel_pri) {
    int j = threadIdx.x;   // 384 threads
    if (j >= 384) return;
    float val;
    if (j < 128) {
        val = bq[j] * rel_pri[j >> 4] * 0.25f;
    } else {
        int jj = (j - 128) & 127;
        const float* b = (j < 256) ? bk : bv;
        const float* R = (j < 256) ? rel_att : rel_msg;
        int hh = jj >> 4, e = jj & 15;
        float s = 0.f;
#pragma unroll
        for (int d2 = 0; d2 < 16; d2++)
            s += b[hh * 16 + d2] * R[hh * 256 + d2 * 16 + e];
        val = s;
    }
    g_beff[j] = val;
}

// ---------------- CSR build ----------------
__global__ void hist_kernel(const int* __restrict__ dst, int E) {
    int e = blockIdx.x * blockDim.x + threadIdx.x;
    if (e < E) atomicAdd(&g_cnt[dst[e]], 1);
}

__global__ void scan1_kernel() {
    __shared__ int sdata[SCAN_BS];
    int tid = threadIdx.x;
    int i = blockIdx.x * SCAN_BS + tid;
    int v = (i < N_NODES) ? g_cnt[i] : 0;
    sdata[tid] = v;
    __syncthreads();
#pragma unroll
    for (int off = 1; off < SCAN_BS; off <<= 1) {
        int x = (tid >= off) ? sdata[tid - off] : 0;
        __syncthreads();
        sdata[tid] += x;
        __syncthreads();
    }
    if (i < N_NODES) g_rowstart[i] = sdata[tid] - v;
    if (tid == SCAN_BS - 1) g_bsums[blockIdx.x] = sdata[tid];
}

__global__ void scan2_kernel() {
    __shared__ int sdata[256];
    int tid = threadIdx.x;
    int v = (tid < NB) ? g_bsums[tid] : 0;
    sdata[tid] = v;
    __syncthreads();
#pragma unroll
    for (int off = 1; off < 256; off <<= 1) {
        int x = (tid >= off) ? sdata[tid - off] : 0;
        __syncthreads();
        sdata[tid] += x;
        __syncthreads();
    }
    g_bsums[tid] = sdata[tid] - v;
}

__global__ void scan3_kernel() {
    int i = blockIdx.x * SCAN_BS + threadIdx.x;
    if (i < N_NODES) {
        int r = g_rowstart[i] + g_bsums[i >> 9];
        g_rowstart[i] = r;
        g_cursor[i] = r;
    }
}

__global__ void scatter_kernel(const int* __restrict__ src, const int* __restrict__ dst, int E) {
    int e = blockIdx.x * blockDim.x + threadIdx.x;
    if (e < E) {
        int p = atomicAdd(&g_cursor[dst[e]], 1);
        g_csr_src[p] = src[e];
    }
}

// ---------------- wmma GEMM: C = A(fp16) @ [Whi|Wlo]^T, 2-term split ----------------
// MODE 0: A = h, W = g_Wbhi/lo (3 n-tiles in-block loop), +bias -> g_q fp32 / g_kv fp16
// MODE 1: A = g_t, W = g_Wahi/lo, out = alpha*(acc+ba) + (1-alpha)*h
#define ALD 136                               // fp16 leading dim (272B rows)
#define CLD 132                               // f32 C leading dim
#define SM_A   0                              // A fp16: 128*136*2 = 34816
#define SM_BHI (128 * ALD * 2)                // 34816
#define SM_BLO (2 * 128 * ALD * 2)            // 69632
#define SM_C   SM_BHI                         // C (128*132*4=67584) aliases Bhi+Blo (69632)
#define TC_SMEM (3 * 128 * ALD * 2)           // 104448 -> 2 blocks/SM

template <int MODE>
__global__ void __launch_bounds__(256, 2)
tc_gemm(const float* __restrict__ Ain, int nrows,
        const float* __restrict__ ba, const float* __restrict__ haux,
        const float* __restrict__ skip, float* __restrict__ outp) {
    constexpr int NT = (MODE == 0) ? 3 : 1;
    extern __shared__ char smem[];
    __half* As = (__half*)(smem + SM_A);
    __half* Bh = (__half*)(smem + SM_BHI);
    __half* Bl = (__half*)(smem + SM_BLO);
    float*  Cs = (float*)(smem + SM_C);

    const int tid = threadIdx.x;
    const int wid = tid >> 5;
    const int m0 = blockIdx.x * 128;
    const int warp_m = wid & 3;        // 4 warps over M (32 rows each)
    const int warp_n = wid >> 2;       // 2 warps over N (64 cols each)

    // ---- load A tile (fp32 -> fp16 single) ----
    {
        const float* Ap = (MODE == 0) ? Ain : g_t;
        int row = tid >> 1;
        int c0 = (tid & 1) << 6;
        bool vrow = (m0 + row) < nrows;
        const float* arow = Ap + (size_t)(m0 + row) * DD + c0;
        __half* as = As + row * ALD + c0;
#pragma unroll
        for (int cc = 0; cc < 16; cc++) {
            float4 v = vrow ? *(const float4*)(arow + cc * 4) : make_float4(0.f, 0.f, 0.f, 0.f);
            __half2 p01 = __floats2half2_rn(v.x, v.y);
            __half2 p23 = __floats2half2_rn(v.z, v.w);
            *(uint2*)(as + cc * 4) = make_uint2(*(unsigned*)&p01, *(unsigned*)&p23);
        }
    }

    float alpha = 0.f, beta = 0.f;
    if (MODE == 1) {
        float s = __ldg(skip);
        alpha = 1.f / (1.f + __expf(-s));
        beta = 1.f - alpha;
    }

    for (int nt = 0; nt < NT; nt++) {
        __syncthreads();
        // ---- load B n-tile (128x128 fp16 hi/lo) ----
        {
            const uint4* sh = (const uint4*)((MODE == 0) ? (g_Wbhi + nt * 16384) : g_Wahi);
            const uint4* sl = (const uint4*)((MODE == 0) ? (g_Wblo + nt * 16384) : g_Walo);
#pragma unroll
            for (int i = 0; i < 8; i++) {
                int u = tid + i * 256;        // 0..2047 (128x128 half = 2048 uint4)
                int j = u >> 4, q = u & 15;
                *(uint4*)((char*)Bh + j * (ALD * 2) + q * 16) = sh[u];
                *(uint4*)((char*)Bl + j * (ALD * 2) + q * 16) = sl[u];
            }
        }
        __syncthreads();

        // ---- wmma mainloop: warp tile 32x64, acc = A*Bh + A*Bl ----
        wmma::fragment<wmma::accumulator, 16, 16, 16, float> acc[2][4];
#pragma unroll
        for (int i = 0; i < 2; i++)
#pragma unroll
            for (int j = 0; j < 4; j++) wmma::fill_fragment(acc[i][j], 0.f);

#pragma unroll 1
        for (int ks = 0; ks < 8; ks++) {
            const int kk = ks * 16;
            wmma::fragment<wmma::matrix_a, 16, 16, 16, __half, wmma::row_major> af[2];
#pragma unroll
            for (int i = 0; i < 2; i++)
                wmma::load_matrix_sync(af[i], As + (warp_m * 32 + i * 16) * ALD + kk, ALD);
#pragma unroll
            for (int j = 0; j < 4; j++) {
                wmma::fragment<wmma::matrix_b, 16, 16, 16, __half, wmma::col_major> bh, bl;
                wmma::load_matrix_sync(bh, Bh + (warp_n * 64 + j * 16) * ALD + kk, ALD);
                wmma::load_matrix_sync(bl, Bl + (warp_n * 64 + j * 16) * ALD + kk, ALD);
#pragma unroll
                for (int i = 0; i < 2; i++) {
                    wmma::mma_sync(acc[i][j], af[i], bh, acc[i][j]);
                    wmma::mma_sync(acc[i][j], af[i], bl, acc[i][j]);
                }
            }
        }

        // ---- stage accumulators to C smem (aliases B; mma reads done) ----
        __syncthreads();
#pragma unroll
        for (int i = 0; i < 2; i++)
#pragma unroll
            for (int j = 0; j < 4; j++)
                wmma::store_matrix_sync(Cs + (warp_m * 32 + i * 16) * CLD + warp_n * 64 + j * 16,
                                        acc[i][j], CLD, wmma::mem_row_major);
        __syncthreads();

        // ---- epilogue: coalesced writes from C smem ----
        {
            int row = tid >> 1;
            int c0 = (tid & 1) << 6;
            int grow = m0 + row;
            if (grow < nrows) {
                const float* crow = Cs + row * CLD + c0;
                const int jb = nt * 128 + c0;
                if (MODE == 0) {
                    if (nt == 0) {
                        float* dst = g_q + (size_t)grow * DD + c0;
#pragma unroll
                        for (int cc = 0; cc < 16; cc++) {
                            float4 o = *(const float4*)(crow + cc * 4);
                            o.x += g_beff[jb + cc * 4];
                            o.y += g_beff[jb + cc * 4 + 1];
                            o.z += g_beff[jb + cc * 4 + 2];
                            o.w += g_beff[jb + cc * 4 + 3];
                            *(float4*)(dst + cc * 4) = o;
                        }
                    } else {
                        __half* dst = g_kv + (size_t)grow * 256 + (nt - 1) * 128 + c0;
#pragma unroll
                        for (int cc = 0; cc < 8; cc++) {
                            uint4 u;
                            unsigned* up = &u.x;
#pragma unroll
                            for (int p = 0; p < 4; p++) {
                                int c = cc * 8 + p * 2;
                                float f0 = crow[c]     + g_beff[jb + c];
                                float f1 = crow[c + 1] + g_beff[jb + c + 1];
                                __half2 hh = __floats2half2_rn(f0, f1);
                                up[p] = *(unsigned*)&hh;
                            }
                            *(uint4*)(dst + cc * 8) = u;
                        }
                    }
                } else {
                    float* dst = outp + (size_t)grow * DD + c0;
                    const float* hrow = haux + (size_t)grow * DD + c0;
#pragma unroll
                    for (int cc = 0; cc < 16; cc++) {
                        float4 hv = *(const float4*)(hrow + cc * 4);
                        float4 o;
                        o.x = alpha * (crow[cc * 4]     + ba[c0 + cc * 4])     + beta * hv.x;
                        o.y = alpha * (crow[cc * 4 + 1] + ba[c0 + cc * 4 + 1]) + beta * hv.y;
                        o.z = alpha * (crow[cc * 4 + 2] + ba[c0 + cc * 4 + 2]) + beta * hv.z;
                        o.w = alpha * (crow[cc * 4 + 3] + ba[c0 + cc * 4 + 3]) + beta * hv.w;
                        *(float4*)(dst + cc * 4) = o;
                    }
                }
            }
        }
    }
}

// ---------------- fused edge softmax + aggregation: one warp per dst node ----------------
__global__ void attn_kernel() {
    int w = (blockIdx.x * blockDim.x + threadIdx.x) >> 5;
    int t = threadIdx.x & 31;
    if (w >= N_NODES) return;
    const int d = w;

    float4 q4 = *(const float4*)(g_q + (size_t)d * DD + t * 4);
    int start = g_rowstart[d];
    int cnt = g_cnt[d];

    float4 acc = make_float4(0.f, 0.f, 0.f, 0.f);
    float den = 0.f;
    const int* __restrict__ cs = g_csr_src + start;

    int i = 0;
    for (; i + 2 <= cnt; i += 2) {
        int s0 = cs[i];
        int s1 = cs[i + 1];
        const uint2* __restrict__ r0 = reinterpret_cast<const uint2*>(g_kv + (size_t)s0 * 256);
        const uint2* __restrict__ r1 = reinterpret_cast<const uint2*>(g_kv + (size_t)s1 * 256);
        uint2 ku0 = r0[t];
        uint2 vu0 = r0[32 + t];
        uint2 ku1 = r1[t];
        uint2 vu1 = r1[32 + t];

        float2 k01 = __half22float2(*reinterpret_cast<__half2*>(&ku0.x));
        float2 k23 = __half22float2(*reinterpret_cast<__half2*>(&ku0.y));
        float p0 = q4.x * k01.x + q4.y * k01.y + q4.z * k23.x + q4.w * k23.y;
        float2 m01 = __half22float2(*reinterpret_cast<__half2*>(&ku1.x));
        float2 m23 = __half22float2(*reinterpret_cast<__half2*>(&ku1.y));
        float p1 = q4.x * m01.x + q4.y * m01.y + q4.z * m23.x + q4.w * m23.y;

        p0 += __shfl_xor_sync(0xffffffffu, p0, 1);
        p1 += __shfl_xor_sync(0xffffffffu, p1, 1);
        p0 += __shfl_xor_sync(0xffffffffu, p0, 2);
        p1 += __shfl_xor_sync(0xffffffffu, p1, 2);
        float ex0 = __expf(p0);
        float ex1 = __expf(p1);

        float2 v01 = __half22float2(*reinterpret_cast<__half2*>(&vu0.x));
        float2 v23 = __half22float2(*reinterpret_cast<__half2*>(&vu0.y));
        float2 w01 = __half22float2(*reinterpret_cast<__half2*>(&vu1.x));
        float2 w23 = __half22float2(*reinterpret_cast<__half2*>(&vu1.y));
        den += ex0 + ex1;
        acc.x += ex0 * v01.x + ex1 * w01.x;
        acc.y += ex0 * v01.y + ex1 * w01.y;
        acc.z += ex0 * v23.x + ex1 * w23.x;
        acc.w += ex0 * v23.y + ex1 * w23.y;
    }
    if (i < cnt) {
        int s0 = cs[i];
        const uint2* __restrict__ r0 = reinterpret_cast<const uint2*>(g_kv + (size_t)s0 * 256);
        uint2 ku0 = r0[t];
        uint2 vu0 = r0[32 + t];
        float2 k01 = __half22float2(*reinterpret_cast<__half2*>(&ku0.x));
        float2 k23 = __half22float2(*reinterpret_cast<__half2*>(&ku0.y));
        float p0 = q4.x * k01.x + q4.y * k01.y + q4.z * k23.x + q4.w * k23.y;
        p0 += __shfl_xor_sync(0xffffffffu, p0, 1);
        p0 += __shfl_xor_sync(0xffffffffu, p0, 2);
        float ex0 = __expf(p0);
        float2 v01 = __half22float2(*reinterpret_cast<__half2*>(&vu0.x));
        float2 v23 = __half22float2(*reinterpret_cast<__half2*>(&vu0.y));
        den += ex0;
        acc.x += ex0 * v01.x;
        acc.y += ex0 * v01.y;
        acc.z += ex0 * v23.x;
        acc.w += ex0 * v23.y;
    }
    float inv = (cnt > 0) ? (1.f / den) : 0.f;
    float4 o = make_float4(acc.x * inv, acc.y * inv, acc.z * inv, acc.w * inv);
    *(float4*)(g_t + (size_t)d * DD + t * 4) = o;
}

// ---------------- launch ----------------
extern "C" void kernel_launch(void* const* d_in, const int* in_sizes, int n_in,
                              void* d_out, int out_size) {
    const float* h       = (const float*)d_in[0];
    const int*   src     = (const int*)d_in[1];
    const int*   dst     = (const int*)d_in[2];
    const float* Wk      = (const float*)d_in[3];
    const float* bk      = (const float*)d_in[4];
    const float* Wq      = (const float*)d_in[5];
    const float* bq      = (const float*)d_in[6];
    const float* Wv      = (const float*)d_in[7];
    const float* bv      = (const float*)d_in[8];
    const float* Wa      = (const float*)d_in[9];
    const float* ba      = (const float*)d_in[10];
    const float* rel_att = (const float*)d_in[11];
    const float* rel_msg = (const float*)d_in[12];
    const float* rel_pri = (const float*)d_in[13];
    const float* skip    = (const float*)d_in[14];

    const int n = in_sizes[0] / DD;   // 100000
    const int E = in_sizes[1];        // 1600000
    const int ntiles = (n + 127) / 128;

    static cudaStream_t s2 = nullptr;
    static cudaEvent_t ev_fork = nullptr, ev_join = nullptr;
    static bool attr_done = false;
    if (!s2) {
        cudaStreamCreateWithFlags(&s2, cudaStreamNonBlocking);
        cudaEventCreateWithFlags(&ev_fork, cudaEventDisableTiming);
        cudaEventCreateWithFlags(&ev_join, cudaEventDisableTiming);
    }
    if (!attr_done) {
        cudaFuncSetAttribute(tc_gemm<0>, cudaFuncAttributeMaxDynamicSharedMemorySize, TC_SMEM);
        cudaFuncSetAttribute(tc_gemm<1>, cudaFuncAttributeMaxDynamicSharedMemorySize, TC_SMEM);
        attr_done = true;
    }

    // fork: CSR chain on s2
    cudaEventRecord(ev_fork, 0);
    cudaStreamWaitEvent(s2, ev_fork, 0);

    // launch order keeps tc_gemm<0> in ncu's profiled slot (4th launch)
    build_weights<<<256, 256>>>(Wk, Wq, Wv, Wa, rel_att, rel_msg, rel_pri);      // 1
    build_bias<<<1, 384>>>(bk, bq, bv, rel_att, rel_msg, rel_pri);               // 2
    zero_cnt_kernel<<<(N_NODES + 255) / 256, 256, 0, s2>>>();                    // 3
    tc_gemm<0><<<ntiles, 256, TC_SMEM>>>(h, n, nullptr, nullptr, nullptr, nullptr); // 4 <- profiled

    hist_kernel<<<(E + 255) / 256, 256, 0, s2>>>(dst, E);
    scan1_kernel<<<NB, SCAN_BS, 0, s2>>>();
    scan2_kernel<<<1, 256, 0, s2>>>();
    scan3_kernel<<<NB, SCAN_BS, 0, s2>>>();
    scatter_kernel<<<(E + 255) / 256, 256, 0, s2>>>(src, dst, E);
    cudaEventRecord(ev_join, s2);

    // join: attn needs both CSR and projections
    cudaStreamWaitEvent(0, ev_join, 0);
    attn_kernel<<<(n * 32 + 255) / 256, 256>>>();
    tc_gemm<1><<<ntiles, 256, TC_SMEM>>>(nullptr, n, ba, h, skip, (float*)d_out);
}

// round 13
// speedup vs baseline: 1.5443x; 1.1662x over previous
#include <cuda_runtime.h>
#include <cuda_fp16.h>
#include <mma.h>
#include <stdint.h>
#include <math.h>

using namespace nvcuda;

#define N_NODES 100000
#define E_EDGES 1600000
#define DD 128
#define SCAN_BS 512
#define NB ((N_NODES + SCAN_BS - 1) / SCAN_BS)   // 196

// ---------------- scratch (device globals; no allocations) ----------------
__device__ float  g_q [N_NODES * DD];      // [N][128] fp32, rel_pri/sqrt_dk folded in
__device__ __half g_kv[N_NODES * 2 * DD];  // [N][256]: k' (128) then v' (128)
__device__ float  g_t [N_NODES * DD];      // aggregated messages
__device__ __half g_Wb[3 * 128 * 128];     // composed projection weights fp16, [j][k]
__device__ __half g_Wa[128 * 128];         // output weights fp16, [j][k]
__device__ float  g_beff[384];
__device__ int    g_cnt     [N_NODES];
__device__ int    g_rowstart[N_NODES];
__device__ int    g_cursor  [N_NODES];
__device__ int    g_csr_src [E_EDGES];
__device__ int    g_bsums   [256];

// ---------------- zero the histogram ----------------
__global__ void zero_cnt_kernel() {
    int i = blockIdx.x * blockDim.x + threadIdx.x;
    if (i < N_NODES) g_cnt[i] = 0;
}

// ---------------- compose weights -> [j][k] fp16 (+ bias in last block) ----------------
__global__ void build_weights(const float* __restrict__ Wk, const float* __restrict__ Wq,
                              const float* __restrict__ Wv, const float* __restrict__ Wa,
                              const float* __restrict__ bk, const float* __restrict__ bq,
                              const float* __restrict__ bv,
                              const float* __restrict__ rel_att, const float* __restrict__ rel_msg,
                              const float* __restrict__ rel_pri) {
    if (blockIdx.x == 256) {   // bias block
        for (int j = threadIdx.x; j < 384; j += blockDim.x) {
            float val;
            if (j < 128) {
                val = bq[j] * rel_pri[j >> 4] * 0.25f;
            } else {
                int jj = (j - 128) & 127;
                const float* b = (j < 256) ? bk : bv;
                const float* R = (j < 256) ? rel_att : rel_msg;
                int hh = jj >> 4, e = jj & 15;
                float s = 0.f;
#pragma unroll
                for (int d2 = 0; d2 < 16; d2++)
                    s += b[hh * 16 + d2] * R[hh * 256 + d2 * 16 + e];
                val = s;
            }
            g_beff[j] = val;
        }
        return;
    }
    int idx = blockIdx.x * blockDim.x + threadIdx.x;   // 65536 threads
    int j = idx >> 7;        // 0..511
    int k = idx & 127;
    float val;
    if (j < 128) {
        val = Wq[j * DD + k] * rel_pri[j >> 4] * 0.25f;    // rel_pri[h]/sqrt(DK)
    } else if (j < 384) {
        int jj = (j - 128) & 127;
        const float* W = (j < 256) ? Wk : Wv;
        const float* R = (j < 256) ? rel_att : rel_msg;
        int hh = jj >> 4, e = jj & 15;
        float s = 0.f;
#pragma unroll
        for (int d2 = 0; d2 < 16; d2++)
            s += W[(hh * 16 + d2) * DD + k] * R[hh * 256 + d2 * 16 + e];
        val = s;
    } else {
        val = Wa[(j - 384) * DD + k];
    }
    if (j < 384) g_Wb[j * 128 + k] = __float2half_rn(val);
    else         g_Wa[(j - 384) * 128 + k] = __float2half_rn(val);
}

// ---------------- CSR build ----------------
__global__ void hist_kernel(const int* __restrict__ dst, int E) {
    int e = blockIdx.x * blockDim.x + threadIdx.x;
    if (e < E) atomicAdd(&g_cnt[dst[e]], 1);
}

__global__ void scan1_kernel() {
    __shared__ int sdata[SCAN_BS];
    int tid = threadIdx.x;
    int i = blockIdx.x * SCAN_BS + tid;
    int v = (i < N_NODES) ? g_cnt[i] : 0;
    sdata[tid] = v;
    __syncthreads();
#pragma unroll
    for (int off = 1; off < SCAN_BS; off <<= 1) {
        int x = (tid >= off) ? sdata[tid - off] : 0;
        __syncthreads();
        sdata[tid] += x;
        __syncthreads();
    }
    if (i < N_NODES) g_rowstart[i] = sdata[tid] - v;
    if (tid == SCAN_BS - 1) g_bsums[blockIdx.x] = sdata[tid];
}

__global__ void scan2_kernel() {
    __shared__ int sdata[256];
    int tid = threadIdx.x;
    int v = (tid < NB) ? g_bsums[tid] : 0;
    sdata[tid] = v;
    __syncthreads();
#pragma unroll
    for (int off = 1; off < 256; off <<= 1) {
        int x = (tid >= off) ? sdata[tid - off] : 0;
        __syncthreads();
        sdata[tid] += x;
        __syncthreads();
    }
    g_bsums[tid] = sdata[tid] - v;
}

__global__ void scan3_kernel() {
    int i = blockIdx.x * SCAN_BS + threadIdx.x;
    if (i < N_NODES) {
        int r = g_rowstart[i] + g_bsums[i >> 9];
        g_rowstart[i] = r;
        g_cursor[i] = r;
    }
}

__global__ void scatter_kernel(const int* __restrict__ src, const int* __restrict__ dst, int E) {
    int e = blockIdx.x * blockDim.x + threadIdx.x;
    if (e < E) {
        int p = atomicAdd(&g_cursor[dst[e]], 1);
        g_csr_src[p] = src[e];
    }
}

// ---------------- wmma GEMM: C = A(fp16) @ W(fp16)^T ----------------
// MODE 0: A = h, W = g_Wb (3 n-tiles in-block loop), +bias -> g_q fp32 / g_kv fp16
// MODE 1: A = g_t, W = g_Wa, out = alpha*(acc+ba) + (1-alpha)*h
#define ALD 136                               // fp16 leading dim (272B rows)
#define CLD 132                               // f32 C leading dim
#define SM_A   0                              // A fp16: 128*136*2 = 34816
#define SM_B   (128 * ALD * 2)                // 34816
#define SM_C   SM_B                           // C half-tile (64*132*4=33792) aliases B
#define TC_SMEM (2 * 128 * ALD * 2)           // 69632 -> 2 blocks/SM (reg-capped at 128)

template <int MODE>
__global__ void __launch_bounds__(256, 2)
tc_gemm(const float* __restrict__ Ain, int mbase, int nlimit,
        const float* __restrict__ ba, const float* __restrict__ haux,
        const float* __restrict__ skip, float* __restrict__ outp) {
    constexpr int NT = (MODE == 0) ? 3 : 1;
    extern __shared__ char smem[];
    __half* As = (__half*)(smem + SM_A);
    __half* Bs = (__half*)(smem + SM_B);
    float*  Cs = (float*)(smem + SM_C);

    const int tid = threadIdx.x;
    const int wid = tid >> 5;
    const int m0 = mbase + blockIdx.x * 128;
    const int warp_m = wid & 3;        // 4 warps over M (32 rows each)
    const int warp_n = wid >> 2;       // 2 warps over N (64 cols each)

    // ---- load A tile (fp32 -> fp16) ----
    {
        const float* Ap = (MODE == 0) ? Ain : g_t;
        int row = tid >> 1;
        int c0 = (tid & 1) << 6;
        bool vrow = (m0 + row) < nlimit;
        const float* arow = Ap + (size_t)(m0 + row) * DD + c0;
        __half* as = As + row * ALD + c0;
#pragma unroll
        for (int cc = 0; cc < 16; cc++) {
            float4 v = vrow ? *(const float4*)(arow + cc * 4) : make_float4(0.f, 0.f, 0.f, 0.f);
            __half2 p01 = __floats2half2_rn(v.x, v.y);
            __half2 p23 = __floats2half2_rn(v.z, v.w);
            *(uint2*)(as + cc * 4) = make_uint2(*(unsigned*)&p01, *(unsigned*)&p23);
        }
    }

    float alpha = 0.f, beta = 0.f;
    if (MODE == 1) {
        float s = __ldg(skip);
        alpha = 1.f / (1.f + __expf(-s));
        beta = 1.f - alpha;
    }

    for (int nt = 0; nt < NT; nt++) {
        __syncthreads();
        // ---- load B n-tile (128x128 fp16) ----
        {
            const uint4* sw = (const uint4*)((MODE == 0) ? (g_Wb + nt * 16384) : g_Wa);
#pragma unroll
            for (int i = 0; i < 8; i++) {
                int u = tid + i * 256;        // 0..2047
                int j = u >> 4, q = u & 15;
                *(uint4*)((char*)Bs + j * (ALD * 2) + q * 16) = sw[u];
            }
        }
        __syncthreads();

        // ---- wmma mainloop: warp tile 32x64, single-term fp16 ----
        wmma::fragment<wmma::accumulator, 16, 16, 16, float> acc[2][4];
#pragma unroll
        for (int i = 0; i < 2; i++)
#pragma unroll
            for (int j = 0; j < 4; j++) wmma::fill_fragment(acc[i][j], 0.f);

#pragma unroll 1
        for (int ks = 0; ks < 8; ks++) {
            const int kk = ks * 16;
            wmma::fragment<wmma::matrix_a, 16, 16, 16, __half, wmma::row_major> af[2];
#pragma unroll
            for (int i = 0; i < 2; i++)
                wmma::load_matrix_sync(af[i], As + (warp_m * 32 + i * 16) * ALD + kk, ALD);
#pragma unroll
            for (int j = 0; j < 4; j++) {
                wmma::fragment<wmma::matrix_b, 16, 16, 16, __half, wmma::col_major> bf;
                wmma::load_matrix_sync(bf, Bs + (warp_n * 64 + j * 16) * ALD + kk, ALD);
#pragma unroll
                for (int i = 0; i < 2; i++)
                    wmma::mma_sync(acc[i][j], af[i], bf, acc[i][j]);
            }
        }

        // ---- two-pass epilogue: stage 64 rows into Cs (aliases dead B), write out ----
#pragma unroll 1
        for (int p = 0; p < 2; p++) {
            __syncthreads();
            if ((warp_m >> 1) == p) {
                int lm = (warp_m & 1) * 32;
#pragma unroll
                for (int i = 0; i < 2; i++)
#pragma unroll
                    for (int j = 0; j < 4; j++)
                        wmma::store_matrix_sync(Cs + (lm + i * 16) * CLD + warp_n * 64 + j * 16,
                                                acc[i][j], CLD, wmma::mem_row_major);
            }
            __syncthreads();
            int l2 = tid >> 2;
            int c0 = (tid & 3) << 5;
            int grow = m0 + p * 64 + l2;
            if (grow < nlimit) {
                const float* crow = Cs + l2 * CLD + c0;
                const int jb = nt * 128 + c0;
                if (MODE == 0) {
                    if (nt == 0) {
                        float* dst = g_q + (size_t)grow * DD + c0;
#pragma unroll
                        for (int cc = 0; cc < 8; cc++) {
                            float4 o = *(const float4*)(crow + cc * 4);
                            o.x += g_beff[jb + cc * 4];
                            o.y += g_beff[jb + cc * 4 + 1];
                            o.z += g_beff[jb + cc * 4 + 2];
                            o.w += g_beff[jb + cc * 4 + 3];
                            *(float4*)(dst + cc * 4) = o;
                        }
                    } else {
                        __half* dst = g_kv + (size_t)grow * 256 + (nt - 1) * 128 + c0;
#pragma unroll
                        for (int cc = 0; cc < 4; cc++) {
                            uint4 u;
                            unsigned* up = &u.x;
#pragma unroll
                            for (int q = 0; q < 4; q++) {
                                int c = cc * 8 + q * 2;
                                float f0 = crow[c]     + g_beff[jb + c];
                                float f1 = crow[c + 1] + g_beff[jb + c + 1];
                                __half2 hh = __floats2half2_rn(f0, f1);
                                up[q] = *(unsigned*)&hh;
                            }
                            *(uint4*)(dst + cc * 8) = u;
                        }
                    }
                } else {
                    float* dst = outp + (size_t)grow * DD + c0;
                    const float* hrow = haux + (size_t)grow * DD + c0;
#pragma unroll
                    for (int cc = 0; cc < 8; cc++) {
                        float4 hv = *(const float4*)(hrow + cc * 4);
                        float4 o;
                        o.x = alpha * (crow[cc * 4]     + ba[c0 + cc * 4])     + beta * hv.x;
                        o.y = alpha * (crow[cc * 4 + 1] + ba[c0 + cc * 4 + 1]) + beta * hv.y;
                        o.z = alpha * (crow[cc * 4 + 2] + ba[c0 + cc * 4 + 2]) + beta * hv.z;
                        o.w = alpha * (crow[cc * 4 + 3] + ba[c0 + cc * 4 + 3]) + beta * hv.w;
                        *(float4*)(dst + cc * 4) = o;
                    }
                }
            }
        }
    }
}

// ---------------- fused edge softmax + aggregation: one warp per dst node ----------------
__global__ void attn_kernel(int base, int count) {
    int w = (blockIdx.x * blockDim.x + threadIdx.x) >> 5;
    int t = threadIdx.x & 31;
    if (w >= count) return;
    const int d = base + w;

    float4 q4 = *(const float4*)(g_q + (size_t)d * DD + t * 4);
    int start = g_rowstart[d];
    int cnt = g_cnt[d];

    float4 acc = make_float4(0.f, 0.f, 0.f, 0.f);
    float den = 0.f;
    const int* __restrict__ cs = g_csr_src + start;

    int i = 0;
    for (; i + 2 <= cnt; i += 2) {
        int s0 = cs[i];
        int s1 = cs[i + 1];
        const uint2* __restrict__ r0 = reinterpret_cast<const uint2*>(g_kv + (size_t)s0 * 256);
        const uint2* __restrict__ r1 = reinterpret_cast<const uint2*>(g_kv + (size_t)s1 * 256);
        uint2 ku0 = r0[t];
        uint2 vu0 = r0[32 + t];
        uint2 ku1 = r1[t];
        uint2 vu1 = r1[32 + t];

        float2 k01 = __half22float2(*reinterpret_cast<__half2*>(&ku0.x));
        float2 k23 = __half22float2(*reinterpret_cast<__half2*>(&ku0.y));
        float p0 = q4.x * k01.x + q4.y * k01.y + q4.z * k23.x + q4.w * k23.y;
        float2 m01 = __half22float2(*reinterpret_cast<__half2*>(&ku1.x));
        float2 m23 = __half22float2(*reinterpret_cast<__half2*>(&ku1.y));
        float p1 = q4.x * m01.x + q4.y * m01.y + q4.z * m23.x + q4.w * m23.y;

        p0 += __shfl_xor_sync(0xffffffffu, p0, 1);
        p1 += __shfl_xor_sync(0xffffffffu, p1, 1);
        p0 += __shfl_xor_sync(0xffffffffu, p0, 2);
        p1 += __shfl_xor_sync(0xffffffffu, p1, 2);
        float ex0 = __expf(p0);
        float ex1 = __expf(p1);

        float2 v01 = __half22float2(*reinterpret_cast<__half2*>(&vu0.x));
        float2 v23 = __half22float2(*reinterpret_cast<__half2*>(&vu0.y));
        float2 w01 = __half22float2(*reinterpret_cast<__half2*>(&vu1.x));
        float2 w23 = __half22float2(*reinterpret_cast<__half2*>(&vu1.y));
        den += ex0 + ex1;
        acc.x += ex0 * v01.x + ex1 * w01.x;
        acc.y += ex0 * v01.y + ex1 * w01.y;
        acc.z += ex0 * v23.x + ex1 * w23.x;
        acc.w += ex0 * v23.y + ex1 * w23.y;
    }
    if (i < cnt) {
        int s0 = cs[i];
        const uint2* __restrict__ r0 = reinterpret_cast<const uint2*>(g_kv + (size_t)s0 * 256);
        uint2 ku0 = r0[t];
        uint2 vu0 = r0[32 + t];
        float2 k01 = __half22float2(*reinterpret_cast<__half2*>(&ku0.x));
        float2 k23 = __half22float2(*reinterpret_cast<__half2*>(&ku0.y));
        float p0 = q4.x * k01.x + q4.y * k01.y + q4.z * k23.x + q4.w * k23.y;
        p0 += __shfl_xor_sync(0xffffffffu, p0, 1);
        p0 += __shfl_xor_sync(0xffffffffu, p0, 2);
        float ex0 = __expf(p0);
        float2 v01 = __half22float2(*reinterpret_cast<__half2*>(&vu0.x));
        float2 v23 = __half22float2(*reinterpret_cast<__half2*>(&vu0.y));
        den += ex0;
        acc.x += ex0 * v01.x;
        acc.y += ex0 * v01.y;
        acc.z += ex0 * v23.x;
        acc.w += ex0 * v23.y;
    }
    float inv = (cnt > 0) ? (1.f / den) : 0.f;
    float4 o = make_float4(acc.x * inv, acc.y * inv, acc.z * inv, acc.w * inv);
    *(float4*)(g_t + (size_t)d * DD + t * 4) = o;
}

// ---------------- launch ----------------
extern "C" void kernel_launch(void* const* d_in, const int* in_sizes, int n_in,
                              void* d_out, int out_size) {
    const float* h       = (const float*)d_in[0];
    const int*   src     = (const int*)d_in[1];
    const int*   dst     = (const int*)d_in[2];
    const float* Wk      = (const float*)d_in[3];
    const float* bk      = (const float*)d_in[4];
    const float* Wq      = (const float*)d_in[5];
    const float* bq      = (const float*)d_in[6];
    const float* Wv      = (const float*)d_in[7];
    const float* bv      = (const float*)d_in[8];
    const float* Wa      = (const float*)d_in[9];
    const float* ba      = (const float*)d_in[10];
    const float* rel_att = (const float*)d_in[11];
    const float* rel_msg = (const float*)d_in[12];
    const float* rel_pri = (const float*)d_in[13];
    const float* skip    = (const float*)d_in[14];

    const int n = in_sizes[0] / DD;   // 100000
    const int E = in_sizes[1];        // 1600000
    const int ntiles = (n + 127) / 128;          // 782
    const int half = (ntiles / 2) * 128;         // 50048 (391 tiles)
    const int tiles0 = half / 128;               // 391
    const int tiles1 = ntiles - tiles0;          // 391

    static cudaStream_t s2 = nullptr;
    static cudaEvent_t ev_fork = nullptr, ev_join = nullptr, ev_a0 = nullptr, ev_g0 = nullptr;
    static bool attr_done = false;
    if (!s2) {
        cudaStreamCreateWithFlags(&s2, cudaStreamNonBlocking);
        cudaEventCreateWithFlags(&ev_fork, cudaEventDisableTiming);
        cudaEventCreateWithFlags(&ev_join, cudaEventDisableTiming);
        cudaEventCreateWithFlags(&ev_a0, cudaEventDisableTiming);
        cudaEventCreateWithFlags(&ev_g0, cudaEventDisableTiming);
    }
    if (!attr_done) {
        cudaFuncSetAttribute(tc_gemm<0>, cudaFuncAttributeMaxDynamicSharedMemorySize, TC_SMEM);
        cudaFuncSetAttribute(tc_gemm<1>, cudaFuncAttributeMaxDynamicSharedMemorySize, TC_SMEM);
        attr_done = true;
    }

    // fork: CSR chain on s2
    cudaEventRecord(ev_fork, 0);
    cudaStreamWaitEvent(s2, ev_fork, 0);

    // launch order keeps tc_gemm<0> in ncu's profiled slot (4th launch)
    zero_cnt_kernel<<<(N_NODES + 255) / 256, 256, 0, s2>>>();                    // 1
    hist_kernel<<<(E + 255) / 256, 256, 0, s2>>>(dst, E);                        // 2
    build_weights<<<257, 256>>>(Wk, Wq, Wv, Wa, bk, bq, bv,
                                rel_att, rel_msg, rel_pri);                      // 3
    tc_gemm<0><<<ntiles, 256, TC_SMEM>>>(h, 0, n, nullptr, nullptr, nullptr, nullptr); // 4 <- profiled

    scan1_kernel<<<NB, SCAN_BS, 0, s2>>>();
    scan2_kernel<<<1, 256, 0, s2>>>();
    scan3_kernel<<<NB, SCAN_BS, 0, s2>>>();
    scatter_kernel<<<(E + 255) / 256, 256, 0, s2>>>(src, dst, E);
    cudaEventRecord(ev_join, s2);

    // join: attn needs both CSR and projections
    cudaStreamWaitEvent(0, ev_join, 0);

    // chunked tail: attn(c0) -> [gemm1(c0) on s2 || attn(c1)] -> gemm1(c1)
    attn_kernel<<<(half * 32 + 255) / 256, 256>>>(0, half);
    cudaEventRecord(ev_a0, 0);
    cudaStreamWaitEvent(s2, ev_a0, 0);
    tc_gemm<1><<<tiles0, 256, TC_SMEM, s2>>>(nullptr, 0, half, ba, h, skip, (float*)d_out);
    cudaEventRecord(ev_g0, s2);

    attn_kernel<<<((n - half) * 32 + 255) / 256, 256>>>(half, n - half);
    tc_gemm<1><<<tiles1, 256, TC_SMEM>>>(nullptr, half, n, ba, h, skip, (float*)d_out);
    cudaStreamWaitEvent(0, ev_g0, 0);
}